// round 14
// baseline (speedup 1.0000x reference)
#include <cuda_runtime.h>
#include <math.h>
#include <stdint.h>

#define BB 128
#define SS 200
#define QQ 20000
#define VV 128
#define KK 128
#define CC 64
#define SUMD 128
#define NROWS (BB*SS)

// Sliced per-(b,slice,s) record: [negE(32) | A(32) | W(64)] = 128 floats = 512B
#define NSLICE 4
#define SLICEV 32
#define RECF 128
#define RECB (RECF*4)
#define SCAN_SMEM (SS*RECB)          // 102,400 B

// precompute geometry: CTA = 64 rows x 320 cols, 640 threads, tile 8r x 4c
// A row-paired in smem, W TMA'd raw then duplicated ((w,w)) per chunk.
#define PROWS 64
#define PT 640
#define KCH 16
#define NKCH (KK/KCH)                // 8
#define WCH_E (KCH*VV*4)             // 8192 B
#define WCH_K (KCH*CC*4)             // 4096 B
#define WCH_TOT (2*WCH_E + WCH_K)    // 20480 B
#define NCOLS 320
// dyn smem float offsets
#define OFF_QK   (PROWS*KK)          // sIV2: 32 pairs x 128 k float2 = 8192 floats
#define OFF_WE   (2*PROWS*KK)        // 16384
#define OFF_WA   (OFF_WE + 2*KCH*VV) // 20480
#define OFF_WK   (OFF_WA + 2*KCH*VV) // 24576
#define OFF_WD   (OFF_WK + 2*KCH*CC) // 26624  dupW: 16 k x 320 c float2 = 10240 floats
#define OFF_MB   (OFF_WD + 2*KCH*NCOLS) // 36864
#define PRE_SMEM ((OFF_MB + 4)*4)    // ~147.5 KB

__device__ float g_slice[(size_t)BB * NSLICE * SS * RECF];   // 52.4 MB
__device__ float g_mem[(size_t)BB * VV * CC];                // 4 MB

typedef unsigned long long ull;

__device__ __forceinline__ ull fma2(ull a, ull b, ull c) {
    ull d;
    asm("fma.rn.f32x2 %0, %1, %2, %3;" : "=l"(d) : "l"(a), "l"(b), "l"(c));
    return d;
}
__device__ __forceinline__ ull pack2(float x, float y) {
    ull d;
    asm("mov.b64 %0, {%1, %2};" : "=l"(d) : "f"(x), "f"(y));
    return d;
}
__device__ __forceinline__ float2 unpack2(ull v) {
    float2 r;
    asm("mov.b64 {%0, %1}, %2;" : "=f"(r.x), "=f"(r.y) : "l"(v));
    return r;
}
__device__ __forceinline__ uint32_t smem_u32(const void* p) {
    uint32_t a;
    asm("{ .reg .u64 t; cvta.to.shared.u64 t, %1; cvt.u32.u64 %0, t; }" : "=r"(a) : "l"(p));
    return a;
}
__device__ __forceinline__ void mbar_init(uint32_t mbar, uint32_t cnt) {
    asm volatile("mbarrier.init.shared.b64 [%0], %1;" :: "r"(mbar), "r"(cnt) : "memory");
}
__device__ __forceinline__ void mbar_expect_tx(uint32_t mbar, uint32_t bytes) {
    asm volatile("mbarrier.arrive.expect_tx.shared.b64 _, [%0], %1;" :: "r"(mbar), "r"(bytes) : "memory");
}
__device__ __forceinline__ void mbar_wait(uint32_t mbar, uint32_t parity) {
    asm volatile(
        "{\n\t.reg .pred P;\n"
        "WAITLOOP_%=:\n\t"
        "mbarrier.try_wait.parity.acquire.cta.shared::cta.b64 P, [%0], %1, 0x989680;\n\t"
        "@P bra.uni WAITDONE_%=;\n\t"
        "bra.uni WAITLOOP_%=;\n"
        "WAITDONE_%=:\n\t}"
        :: "r"(mbar), "r"(parity) : "memory");
}
__device__ __forceinline__ void bulk_g2s(uint32_t dst, const void* src, uint32_t bytes, uint32_t mbar) {
    asm volatile(
        "cp.async.bulk.shared::cta.global.mbarrier::complete_tx::bytes [%0], [%1], %2, [%3];"
        :: "r"(dst), "l"(src), "r"(bytes), "r"(mbar) : "memory");
}

// ---------------------------------------------------------------------------
// Kernel A v5: precompute GEMM, zero-mov inner loop.
// 640 threads: tr = t/80 -> 8 rows (4 row-pairs), tc = t%80 -> 4 cols.
// A row-paired ((a_r0,a_r1) float2), W duplicated ((w,w) float2).
// Per 2-k: 8 LDS.128 + 32 FMA2.
// ---------------------------------------------------------------------------
__global__ __launch_bounds__(PT) void precompute_kernel(
    const float* __restrict__ q_emb,
    const float* __restrict__ i_emb,
    const float* __restrict__ key_memory,
    const float* __restrict__ erase_W,
    const float* __restrict__ erase_b,
    const float* __restrict__ add_W,
    const float* __restrict__ add_b,
    const int*   __restrict__ input)
{
    extern __shared__ __align__(16) float psm[];
    float2* sIV2 = (float2*)psm;                 // [32 pairs][128 k]
    float2* sQK2 = (float2*)(psm + OFF_QK);
    float*  sWE  = psm + OFF_WE;                 // raw TMA [2][16][128]
    float*  sWA  = psm + OFF_WA;
    float*  sWK  = psm + OFF_WK;                 // raw TMA [2][16][64]
    float2* sWD  = (float2*)(psm + OFF_WD);      // dup [16][320]
    const uint32_t mb = smem_u32(psm + OFF_MB);

    __shared__ float sLg[PROWS][68];
    __shared__ int   sIdx[PROWS];

    const int t    = threadIdx.x;
    const int lane = t & 31;
    const int wid  = t >> 5;
    const int tr   = t / 80;                     // 0..7 -> rows tr*8..tr*8+8
    const int tc   = t % 80;                     // 4 cols
    const int row0 = blockIdx.x * PROWS;

    if (t < PROWS) sIdx[t] = input[row0 + t];
    if (t == 0) {
        mbar_init(mb, 1);
        asm volatile("fence.proxy.async.shared::cta;" ::: "memory");
        mbar_expect_tx(mb, WCH_TOT);
        bulk_g2s(smem_u32(sWE), erase_W,    WCH_E, mb);
        bulk_g2s(smem_u32(sWA), add_W,      WCH_E, mb);
        bulk_g2s(smem_u32(sWK), key_memory, WCH_K, mb);
    }
    __syncthreads();

    // Gather embeddings into row-pair layout.
    for (int r = wid; r < PROWS; r += PT/32) {
        const int idx = sIdx[r];
        const int qid = idx > QQ ? idx - QQ : idx;
        float4 v  = *((const float4*)(i_emb + (size_t)idx * VV) + lane);
        float4 qv = *((const float4*)(q_emb + (size_t)qid * KK) + lane);
        const int pr = r >> 1, h = r & 1;
#pragma unroll
        for (int j = 0; j < 4; j++) {
            ((float*)&sIV2[pr * KK + lane * 4 + j])[h] = ((const float*)&v)[j];
            ((float*)&sQK2[pr * KK + lane * 4 + j])[h] = ((const float*)&qv)[j];
        }
    }

    // per-thread operand selection: global col c0 (0..319), 4 cols
    const int cglob = tc * 4 + ((tc < 32) ? 0 : (tc < 64) ? 0 : 0); // tc*4 directly
    const float2* Asrc = (tc < 64) ? sIV2 : sQK2;
    const int c0 = tc * 4;                       // column in dupW space (0..319)

    ull acc[4][4];                               // [row-pair][col]
    if (tc < 32) {
        const float4 b4 = *(const float4*)(erase_b + c0);
#pragma unroll
        for (int p = 0; p < 4; p++) {
            acc[p][0] = pack2(b4.x, b4.x); acc[p][1] = pack2(b4.y, b4.y);
            acc[p][2] = pack2(b4.z, b4.z); acc[p][3] = pack2(b4.w, b4.w);
        }
    } else if (tc < 64) {
        const float4 b4 = *(const float4*)(add_b + (c0 - 128));
#pragma unroll
        for (int p = 0; p < 4; p++) {
            acc[p][0] = pack2(b4.x, b4.x); acc[p][1] = pack2(b4.y, b4.y);
            acc[p][2] = pack2(b4.z, b4.z); acc[p][3] = pack2(b4.w, b4.w);
        }
    } else {
        const ull z = pack2(0.f, 0.f);
#pragma unroll
        for (int p = 0; p < 4; p++)
            { acc[p][0] = z; acc[p][1] = z; acc[p][2] = z; acc[p][3] = z; }
    }
    (void)cglob;

    const float2* Ath = Asrc + (tr * 4) * KK;    // 4 row-pairs, stride KK float2

    for (int ch = 0; ch < NKCH; ch++) {
        const int buf = ch & 1;
        mbar_wait(mb, ch & 1);
        __syncthreads();
        if (t == 0 && ch + 1 < NKCH) {
            const int nb = buf ^ 1, k0n = (ch + 1) * KCH;
            mbar_expect_tx(mb, WCH_TOT);
            bulk_g2s(smem_u32(sWE + nb * KCH * VV), erase_W    + k0n * VV, WCH_E, mb);
            bulk_g2s(smem_u32(sWA + nb * KCH * VV), add_W      + k0n * VV, WCH_E, mb);
            bulk_g2s(smem_u32(sWK + nb * KCH * CC), key_memory + k0n * CC, WCH_K, mb);
        }

        // duplicate raw W -> sWD[k][c] = (w,w); 5120 elems / 640 thr = 8 each
        {
            const float* rawE = sWE + buf * KCH * VV;
            const float* rawA = sWA + buf * KCH * VV;
            const float* rawK = sWK + buf * KCH * CC;
#pragma unroll
            for (int i = 0; i < 8; i++) {
                const int idx = t + i * PT;
                const int k = idx / NCOLS, c = idx % NCOLS;
                float v;
                if (c < 128)      v = rawE[k * VV + c];
                else if (c < 256) v = rawA[k * VV + (c - 128)];
                else              v = rawK[k * CC + (c - 256)];
                sWD[k * NCOLS + c] = make_float2(v, v);
            }
        }
        __syncthreads();

        const float2* Wd = sWD + c0;             // stride NCOLS per k
        const float2* A  = Ath + ch * KCH;
#pragma unroll
        for (int kk = 0; kk < KCH; kk += 2) {
            const ulonglong2 wa0 = *(const ulonglong2*)(Wd + kk * NCOLS);        // c0,c0+1 @k
            const ulonglong2 wb0 = *(const ulonglong2*)(Wd + kk * NCOLS + 2);    // c0+2,3 @k
            const ulonglong2 wa1 = *(const ulonglong2*)(Wd + (kk + 1) * NCOLS);
            const ulonglong2 wb1 = *(const ulonglong2*)(Wd + (kk + 1) * NCOLS + 2);
#pragma unroll
            for (int p = 0; p < 4; p++) {
                const ulonglong2 ap = *(const ulonglong2*)(A + p * KK + kk);     // pair @k, @k+1
                acc[p][0] = fma2(ap.x, wa0.x, acc[p][0]);
                acc[p][1] = fma2(ap.x, wa0.y, acc[p][1]);
                acc[p][2] = fma2(ap.x, wb0.x, acc[p][2]);
                acc[p][3] = fma2(ap.x, wb0.y, acc[p][3]);
                acc[p][0] = fma2(ap.y, wa1.x, acc[p][0]);
                acc[p][1] = fma2(ap.y, wa1.y, acc[p][1]);
                acc[p][2] = fma2(ap.y, wb1.x, acc[p][2]);
                acc[p][3] = fma2(ap.y, wb1.y, acc[p][3]);
            }
        }
        __syncthreads();   // all reads of sWD done before next chunk's dup pass
    }

    // ---- Epilogue ----
    if (tc < 64) {
        const bool is_erase = (tc < 32);
        const int cb = is_erase ? c0 : (c0 - 128);   // 0..127
#pragma unroll
        for (int p = 0; p < 4; p++) {
            const int r0g = row0 + tr * 8 + 2 * p;
            const int r1g = r0g + 1;
            const int b0 = r0g / SS, s0 = r0g - b0 * SS;
            const int b1 = r1g / SS, s1 = r1g - b1 * SS;
#pragma unroll
            for (int j = 0; j < 4; j++) {
                const int col = cb + j;
                const int sl = col >> 5;
                const int off = (is_erase ? 0 : 32) + (col & 31);
                float2 f = unpack2(acc[p][j]);
                float v0, v1;
                if (is_erase) {
                    v0 = -1.f / (1.f + __expf(-f.x));
                    v1 = -1.f / (1.f + __expf(-f.y));
                } else {
                    v0 = tanhf(f.x);
                    v1 = tanhf(f.y);
                }
                g_slice[((size_t)(b0 * NSLICE + sl) * SS + s0) * RECF + off] = v0;
                g_slice[((size_t)(b1 * NSLICE + sl) * SS + s1) * RECF + off] = v1;
            }
        }
    } else {
        const int ck = c0 - 256;                     // 0..63
#pragma unroll
        for (int p = 0; p < 4; p++) {
            const int lr = tr * 8 + 2 * p;
#pragma unroll
            for (int j = 0; j < 4; j++) {
                float2 f = unpack2(acc[p][j]);
                sLg[lr    ][ck + j] = f.x;
                sLg[lr + 1][ck + j] = f.y;
            }
        }
    }
    __syncthreads();

    if (t < PROWS) {
        float mx = -1e30f;
#pragma unroll
        for (int c = 0; c < CC; c++) mx = fmaxf(mx, sLg[t][c]);
        float sum = 0.f;
#pragma unroll
        for (int c = 0; c < CC; c++) { float e = __expf(sLg[t][c] - mx); sLg[t][c] = e; sum += e; }
        const float inv = 1.f / sum;
#pragma unroll
        for (int c = 0; c < CC; c++) sLg[t][c] *= inv;
    }
    __syncthreads();

    for (int idx = t; idx < PROWS * (CC / 4); idx += PT) {
        const int r = idx >> 4, q = idx & 15;
        const int gr = row0 + r;
        const int b = gr / SS, s = gr - b * SS;
        const float4 o = *(const float4*)&sLg[r][q * 4];
#pragma unroll
        for (int j = 0; j < NSLICE; j++)
            *(float4*)&g_slice[((size_t)(b * NSLICE + j) * SS + s) * RECF + 64 + q * 4] = o;
    }
}

// ---------------------------------------------------------------------------
// Kernel B: sliced scan (UNCHANGED from passing R10).
// ---------------------------------------------------------------------------
__global__ __launch_bounds__(256) void scan_kernel(
    const float* __restrict__ init_value_memory)
{
    extern __shared__ __align__(16) float dsm[];

    const int bs = blockIdx.x;
    const int sl = bs & 3;
    const int b  = bs >> 2;
    const int t  = threadIdx.x;
    const int pg = t >> 4;
    const int cg = t & 15;

    {
        const float4* src = (const float4*)(g_slice + (size_t)bs * SS * RECF);
        float4* dst = (float4*)dsm;
#pragma unroll
        for (int i = 0; i < 25; i++)
            dst[t + i * 256] = src[t + i * 256];
    }

    const int v0 = sl * SLICEV + pg * 2;
    ull m2[4];
    {
        const float4 ra = *(const float4*)(init_value_memory + (v0    ) * CC + cg * 4);
        const float4 rb = *(const float4*)(init_value_memory + (v0 + 1) * CC + cg * 4);
        m2[0] = pack2(ra.x, rb.x);
        m2[1] = pack2(ra.y, rb.y);
        m2[2] = pack2(ra.z, rb.z);
        m2[3] = pack2(ra.w, rb.w);
    }
    __syncthreads();

    const float* sp = dsm;
#pragma unroll 4
    for (int s = 0; s < SS; s++, sp += RECF) {
        const ull ne = *(const ull*)(sp + pg * 2);
        const ull aa = *(const ull*)(sp + 32 + pg * 2);
        const float4 wf = *(const float4*)(sp + 64 + cg * 4);
        const ull w0 = pack2(wf.x, wf.x);
        const ull w1 = pack2(wf.y, wf.y);
        const ull w2 = pack2(wf.z, wf.z);
        const ull w3 = pack2(wf.w, wf.w);
        m2[0] = fma2(w0, fma2(m2[0], ne, aa), m2[0]);
        m2[1] = fma2(w1, fma2(m2[1], ne, aa), m2[1]);
        m2[2] = fma2(w2, fma2(m2[2], ne, aa), m2[2]);
        m2[3] = fma2(w3, fma2(m2[3], ne, aa), m2[3]);
    }

    float* dst0 = g_mem + ((size_t)b * VV + v0) * CC + cg * 4;
    float* dst1 = dst0 + CC;
    float2 f0 = unpack2(m2[0]), f1 = unpack2(m2[1]), f2 = unpack2(m2[2]), f3 = unpack2(m2[3]);
    float4 oa; oa.x = f0.x; oa.y = f1.x; oa.z = f2.x; oa.w = f3.x;
    float4 ob; ob.x = f0.y; ob.y = f1.y; ob.z = f2.y; ob.w = f3.y;
    *(float4*)dst0 = oa;
    *(float4*)dst1 = ob;
}

// ---------------------------------------------------------------------------
// Kernel C: readout (UNCHANGED from passing R10).
// ---------------------------------------------------------------------------
__global__ __launch_bounds__(256) void readout_kernel(
    const float* __restrict__ q_emb,
    const float* __restrict__ key_memory,
    const float* __restrict__ summ_W,
    const float* __restrict__ summ_b,
    const float* __restrict__ out_W,
    const float* __restrict__ out_b,
    const int*   __restrict__ target_id,
    float* __restrict__ out)
{
    __shared__ float sMem[VV][CC + 1];
    __shared__ float sQv[KK];
    __shared__ float sWt[CC];
    __shared__ float sCat[VV + KK];
    __shared__ float sPart[4][CC + 1];
    __shared__ float sRed[8][SUMD + 4];
    __shared__ float sRed2[4];

    const int b    = blockIdx.x;
    const int t    = threadIdx.x;
    const int lane = t & 31;
    const int wid  = t >> 5;

    const float* gm = g_mem + (size_t)b * VV * CC;
#pragma unroll
    for (int i = 0; i < 8; i++) {
        const int idx = t + i * 256;
        const int v = idx >> 4, q = idx & 15;
        const float4 val = *(const float4*)(gm + v * CC + q * 4);
        sMem[v][q * 4 + 0] = val.x;
        sMem[v][q * 4 + 1] = val.y;
        sMem[v][q * 4 + 2] = val.z;
        sMem[v][q * 4 + 3] = val.w;
    }
    if (t < KK) sQv[t] = q_emb[(size_t)target_id[b] * KK + t];
    __syncthreads();

    {
        const int c = t & 63, kg = t >> 6;
        float acc = 0.f;
#pragma unroll
        for (int j = 0; j < 32; j++)
            acc = fmaf(sQv[kg * 32 + j], __ldg(key_memory + (kg * 32 + j) * CC + c), acc);
        sPart[kg][c] = acc;
    }
    __syncthreads();
    if (t < CC) {
        float s = 0.f;
#pragma unroll
        for (int j = 0; j < 4; j++) s += sPart[j][t];
        sWt[t] = s;
    }
    __syncthreads();
    if (t < 32) {
        float l0 = sWt[t], l1 = sWt[t + 32];
        float mx = fmaxf(l0, l1);
#pragma unroll
        for (int off = 16; off > 0; off >>= 1)
            mx = fmaxf(mx, __shfl_xor_sync(0xffffffffu, mx, off));
        float e0 = __expf(l0 - mx), e1 = __expf(l1 - mx);
        float sm = e0 + e1;
#pragma unroll
        for (int off = 16; off > 0; off >>= 1)
            sm += __shfl_xor_sync(0xffffffffu, sm, off);
        const float inv = 1.f / sm;
        sWt[t] = e0 * inv;
        sWt[t + 32] = e1 * inv;
    }
    __syncthreads();

    if (t < VV) {
        float acc = 0.f;
#pragma unroll
        for (int c = 0; c < CC; c++)
            acc = fmaf(sMem[t][c], sWt[c], acc);
        sCat[t] = acc;
    } else {
        sCat[t] = sQv[t - 128];
    }
    __syncthreads();

    {
        float4 acc4 = make_float4(0.f, 0.f, 0.f, 0.f);
#pragma unroll
        for (int j = 0; j < 32; j++) {
            const int row = wid * 32 + j;
            const float x = sCat[row];
            const float4 wr = *(const float4*)(summ_W + row * SUMD + lane * 4);
            acc4.x = fmaf(x, wr.x, acc4.x);
            acc4.y = fmaf(x, wr.y, acc4.y);
            acc4.z = fmaf(x, wr.z, acc4.z);
            acc4.w = fmaf(x, wr.w, acc4.w);
        }
        *(float4*)&sRed[wid][lane * 4] = acc4;
    }
    __syncthreads();

    if (t < SUMD) {
        float s = 0.f;
#pragma unroll
        for (int j = 0; j < 8; j++) s += sRed[j][t];
        const float sm = tanhf(s + summ_b[t]);
        float p = sm * __ldg(out_W + t);
#pragma unroll
        for (int off = 16; off > 0; off >>= 1)
            p += __shfl_down_sync(0xffffffffu, p, off);
        if (lane == 0) sRed2[wid] = p;
    }
    __syncthreads();
    if (t == 0)
        out[b] = sRed2[0] + sRed2[1] + sRed2[2] + sRed2[3] + out_b[0];
}

// ---------------------------------------------------------------------------
extern "C" void kernel_launch(void* const* d_in, const int* in_sizes, int n_in,
                              void* d_out, int out_size)
{
    const float* q_emb      = (const float*)d_in[0];
    const float* i_emb      = (const float*)d_in[1];
    const float* key_memory = (const float*)d_in[2];
    const float* init_vm    = (const float*)d_in[3];
    const float* erase_W    = (const float*)d_in[4];
    const float* erase_b    = (const float*)d_in[5];
    const float* add_W      = (const float*)d_in[6];
    const float* add_b      = (const float*)d_in[7];
    const float* summ_W     = (const float*)d_in[8];
    const float* summ_b     = (const float*)d_in[9];
    const float* out_W      = (const float*)d_in[10];
    const float* out_b      = (const float*)d_in[11];
    const int*   input      = (const int*)d_in[12];
    const int*   target_id  = (const int*)d_in[13];
    float* out = (float*)d_out;

    cudaFuncSetAttribute(precompute_kernel, cudaFuncAttributeMaxDynamicSharedMemorySize, PRE_SMEM);
    cudaFuncSetAttribute(scan_kernel, cudaFuncAttributeMaxDynamicSharedMemorySize, SCAN_SMEM);

    precompute_kernel<<<NROWS / PROWS, PT, PRE_SMEM>>>(
        q_emb, i_emb, key_memory, erase_W, erase_b, add_W, add_b, input);

    scan_kernel<<<BB * NSLICE, 256, SCAN_SMEM>>>(init_vm);

    readout_kernel<<<BB, 256>>>(
        q_emb, key_memory, summ_W, summ_b, out_W, out_b, target_id, out);
}

// round 16
// speedup vs baseline: 1.1276x; 1.1276x over previous
#include <cuda_runtime.h>
#include <math.h>
#include <stdint.h>

#define BB 128
#define SS 200
#define QQ 20000
#define VV 128
#define KK 128
#define CC 64
#define SUMD 128
#define NROWS (BB*SS)

// Sliced per-(b,slice,s) record: [negE(32) | A(32) | W(64)] = 128 floats = 512B
#define NSLICE 4
#define SLICEV 32
#define RECF 128
#define RECB (RECF*4)
#define SCAN_SMEM (SS*RECB)          // 102,400 B

// precompute geometry: CTA = 64 rows x 320 cols, 640 threads, tile 8r x 4c
// A k-major row-pairs; warp spans 4 tc x 8 tr.
#define PROWS 64
#define PT 640
#define KCH 16
#define NKCH (KK/KCH)                // 8
#define WCH_E (KCH*VV*4)
#define WCH_K (KCH*CC*4)
#define WCH_TOT (2*WCH_E + WCH_K)
#define KP2 34                       // float2 per k (32 pairs + 2 pad), 272B, 16B-mult
// dyn smem float offsets
#define OFF_QK   (KK*KP2*2)          // 8704
#define OFF_WE   (2*KK*KP2*2)        // 17408
#define OFF_WA   (OFF_WE + 2*KCH*VV) // 21504
#define OFF_WK   (OFF_WA + 2*KCH*VV) // 25600
#define OFF_MB   (OFF_WK + 2*KCH*CC) // 27648
#define PRE_SMEM ((OFF_MB + 4)*4)    // ~110.6 KB

__device__ float g_slice[(size_t)BB * NSLICE * SS * RECF];   // 52.4 MB
__device__ float g_mem[(size_t)BB * VV * CC];                // 4 MB

typedef unsigned long long ull;

__device__ __forceinline__ ull fma2(ull a, ull b, ull c) {
    ull d;
    asm("fma.rn.f32x2 %0, %1, %2, %3;" : "=l"(d) : "l"(a), "l"(b), "l"(c));
    return d;
}
__device__ __forceinline__ ull pack2(float x, float y) {
    ull d;
    asm("mov.b64 %0, {%1, %2};" : "=l"(d) : "f"(x), "f"(y));
    return d;
}
__device__ __forceinline__ float2 unpack2(ull v) {
    float2 r;
    asm("mov.b64 {%0, %1}, %2;" : "=f"(r.x), "=f"(r.y) : "l"(v));
    return r;
}
__device__ __forceinline__ uint32_t smem_u32(const void* p) {
    uint32_t a;
    asm("{ .reg .u64 t; cvta.to.shared.u64 t, %1; cvt.u32.u64 %0, t; }" : "=r"(a) : "l"(p));
    return a;
}
__device__ __forceinline__ void mbar_init(uint32_t mbar, uint32_t cnt) {
    asm volatile("mbarrier.init.shared.b64 [%0], %1;" :: "r"(mbar), "r"(cnt) : "memory");
}
__device__ __forceinline__ void mbar_expect_tx(uint32_t mbar, uint32_t bytes) {
    asm volatile("mbarrier.arrive.expect_tx.shared.b64 _, [%0], %1;" :: "r"(mbar), "r"(bytes) : "memory");
}
__device__ __forceinline__ void mbar_wait(uint32_t mbar, uint32_t parity) {
    asm volatile(
        "{\n\t.reg .pred P;\n"
        "WAITLOOP_%=:\n\t"
        "mbarrier.try_wait.parity.acquire.cta.shared::cta.b64 P, [%0], %1, 0x989680;\n\t"
        "@P bra.uni WAITDONE_%=;\n\t"
        "bra.uni WAITLOOP_%=;\n"
        "WAITDONE_%=:\n\t}"
        :: "r"(mbar), "r"(parity) : "memory");
}
__device__ __forceinline__ void bulk_g2s(uint32_t dst, const void* src, uint32_t bytes, uint32_t mbar) {
    asm volatile(
        "cp.async.bulk.shared::cta.global.mbarrier::complete_tx::bytes [%0], [%1], %2, [%3];"
        :: "r"(dst), "l"(src), "r"(bytes), "r"(mbar) : "memory");
}

// ---------------------------------------------------------------------------
// Kernel A v6: precompute GEMM.
// 640 threads: tcg = t>>3 (4 cols), trg = t&7 (8 rows = 4 pairs).
// A k-major row-paired; W raw float4 + 8 dup movs per 2-k.
// Per 2-k: 2 LDS.128 W (1wf) + 4 LDS.128 A (2wf) + 8 movs + 32 FMA2.
// ---------------------------------------------------------------------------
__global__ __launch_bounds__(PT) void precompute_kernel(
    const float* __restrict__ q_emb,
    const float* __restrict__ i_emb,
    const float* __restrict__ key_memory,
    const float* __restrict__ erase_W,
    const float* __restrict__ erase_b,
    const float* __restrict__ add_W,
    const float* __restrict__ add_b,
    const int*   __restrict__ input)
{
    extern __shared__ __align__(16) float psm[];
    float2* sIVk = (float2*)psm;                 // [128 k][34 pairs]
    float2* sQKk = (float2*)(psm + OFF_QK);
    float*  sWE  = psm + OFF_WE;                 // raw TMA [2][16][128]
    float*  sWA  = psm + OFF_WA;
    float*  sWK  = psm + OFF_WK;                 // raw TMA [2][16][64]
    const uint32_t mb = smem_u32(psm + OFF_MB);

    __shared__ float sLg[PROWS][68];
    __shared__ int   sIdx[PROWS];

    const int t    = threadIdx.x;
    const int lane = t & 31;
    const int wid  = t >> 5;
    const int tcg  = t >> 3;                     // 0..79 col group
    const int trg  = t & 7;                      // 0..7 row group
    const int row0 = blockIdx.x * PROWS;

    if (t < PROWS) sIdx[t] = input[row0 + t];
    if (t == 0) {
        mbar_init(mb, 1);
        asm volatile("fence.proxy.async.shared::cta;" ::: "memory");
        mbar_expect_tx(mb, WCH_TOT);
        bulk_g2s(smem_u32(sWE), erase_W,    WCH_E, mb);
        bulk_g2s(smem_u32(sWA), add_W,      WCH_E, mb);
        bulk_g2s(smem_u32(sWK), key_memory, WCH_K, mb);
    }
    __syncthreads();

    // Gather embeddings k-major: warp handles row-pair pr (2 rows, 128 k).
    for (int pr = wid; pr < PROWS / 2; pr += PT / 32) {
        const int i0 = sIdx[2 * pr], i1 = sIdx[2 * pr + 1];
        const int q0 = i0 > QQ ? i0 - QQ : i0;
        const int q1 = i1 > QQ ? i1 - QQ : i1;
#pragma unroll
        for (int kb = 0; kb < KK; kb += 32) {
            const int k = kb + lane;
            const float v0  = i_emb[(size_t)i0 * VV + k];
            const float v1  = i_emb[(size_t)i1 * VV + k];
            const float qv0 = q_emb[(size_t)q0 * KK + k];
            const float qv1 = q_emb[(size_t)q1 * KK + k];
            sIVk[k * KP2 + pr] = make_float2(v0, v1);
            sQKk[k * KP2 + pr] = make_float2(qv0, qv1);
        }
    }
    __syncthreads();

    // per-thread operand selection: 4 cols at c0 (local to its matrix)
    const float2* Abase = (tcg < 64) ? sIVk : sQKk;
    const float* Wbase;
    int wstride, c0;
    if (tcg < 32)      { Wbase = sWE; wstride = VV; c0 = tcg * 4; }
    else if (tcg < 64) { Wbase = sWA; wstride = VV; c0 = (tcg - 32) * 4; }
    else               { Wbase = sWK; wstride = CC; c0 = (tcg - 64) * 4; }

    // acc[p][c]: rows (trg*8+2p, trg*8+2p+1), col c0+c (row-packed)
    ull acc[4][4];
    if (tcg < 32) {
        const float4 b4 = *(const float4*)(erase_b + c0);
#pragma unroll
        for (int p = 0; p < 4; p++) {
            acc[p][0] = pack2(b4.x, b4.x); acc[p][1] = pack2(b4.y, b4.y);
            acc[p][2] = pack2(b4.z, b4.z); acc[p][3] = pack2(b4.w, b4.w);
        }
    } else if (tcg < 64) {
        const float4 b4 = *(const float4*)(add_b + c0);
#pragma unroll
        for (int p = 0; p < 4; p++) {
            acc[p][0] = pack2(b4.x, b4.x); acc[p][1] = pack2(b4.y, b4.y);
            acc[p][2] = pack2(b4.z, b4.z); acc[p][3] = pack2(b4.w, b4.w);
        }
    } else {
        const ull z = pack2(0.f, 0.f);
#pragma unroll
        for (int p = 0; p < 4; p++)
            { acc[p][0] = z; acc[p][1] = z; acc[p][2] = z; acc[p][3] = z; }
    }

    const float2* Ath = Abase + trg * 4;         // pairs trg*4..trg*4+3, +k*KP2

    for (int ch = 0; ch < NKCH; ch++) {
        const int buf = ch & 1;
        mbar_wait(mb, ch & 1);
        __syncthreads();
        if (t == 0 && ch + 1 < NKCH) {
            const int nb = buf ^ 1, k0n = (ch + 1) * KCH;
            mbar_expect_tx(mb, WCH_TOT);
            bulk_g2s(smem_u32(sWE + nb * KCH * VV), erase_W    + k0n * VV, WCH_E, mb);
            bulk_g2s(smem_u32(sWA + nb * KCH * VV), add_W      + k0n * VV, WCH_E, mb);
            bulk_g2s(smem_u32(sWK + nb * KCH * CC), key_memory + k0n * CC, WCH_K, mb);
        }

        const float* W = Wbase + buf * KCH * wstride + c0;
        const float2* A = Ath + (ch * KCH) * KP2;
#pragma unroll
        for (int kk = 0; kk < KCH; kk += 2) {
            const float4 w0 = *(const float4*)(W + kk * wstride);
            const float4 w1 = *(const float4*)(W + (kk + 1) * wstride);
            const ulonglong2 a0a = *(const ulonglong2*)(A + kk * KP2);       // pairs 0,1 @k
            const ulonglong2 a0b = *(const ulonglong2*)(A + kk * KP2 + 2);   // pairs 2,3 @k
            const ulonglong2 a1a = *(const ulonglong2*)(A + (kk + 1) * KP2);
            const ulonglong2 a1b = *(const ulonglong2*)(A + (kk + 1) * KP2 + 2);
            const ull wd00 = pack2(w0.x, w0.x), wd01 = pack2(w0.y, w0.y);
            const ull wd02 = pack2(w0.z, w0.z), wd03 = pack2(w0.w, w0.w);
            const ull wd10 = pack2(w1.x, w1.x), wd11 = pack2(w1.y, w1.y);
            const ull wd12 = pack2(w1.z, w1.z), wd13 = pack2(w1.w, w1.w);

            acc[0][0] = fma2(a0a.x, wd00, acc[0][0]);
            acc[0][1] = fma2(a0a.x, wd01, acc[0][1]);
            acc[0][2] = fma2(a0a.x, wd02, acc[0][2]);
            acc[0][3] = fma2(a0a.x, wd03, acc[0][3]);
            acc[1][0] = fma2(a0a.y, wd00, acc[1][0]);
            acc[1][1] = fma2(a0a.y, wd01, acc[1][1]);
            acc[1][2] = fma2(a0a.y, wd02, acc[1][2]);
            acc[1][3] = fma2(a0a.y, wd03, acc[1][3]);
            acc[2][0] = fma2(a0b.x, wd00, acc[2][0]);
            acc[2][1] = fma2(a0b.x, wd01, acc[2][1]);
            acc[2][2] = fma2(a0b.x, wd02, acc[2][2]);
            acc[2][3] = fma2(a0b.x, wd03, acc[2][3]);
            acc[3][0] = fma2(a0b.y, wd00, acc[3][0]);
            acc[3][1] = fma2(a0b.y, wd01, acc[3][1]);
            acc[3][2] = fma2(a0b.y, wd02, acc[3][2]);
            acc[3][3] = fma2(a0b.y, wd03, acc[3][3]);

            acc[0][0] = fma2(a1a.x, wd10, acc[0][0]);
            acc[0][1] = fma2(a1a.x, wd11, acc[0][1]);
            acc[0][2] = fma2(a1a.x, wd12, acc[0][2]);
            acc[0][3] = fma2(a1a.x, wd13, acc[0][3]);
            acc[1][0] = fma2(a1a.y, wd10, acc[1][0]);
            acc[1][1] = fma2(a1a.y, wd11, acc[1][1]);
            acc[1][2] = fma2(a1a.y, wd12, acc[1][2]);
            acc[1][3] = fma2(a1a.y, wd13, acc[1][3]);
            acc[2][0] = fma2(a1b.x, wd10, acc[2][0]);
            acc[2][1] = fma2(a1b.x, wd11, acc[2][1]);
            acc[2][2] = fma2(a1b.x, wd12, acc[2][2]);
            acc[2][3] = fma2(a1b.x, wd13, acc[2][3]);
            acc[3][0] = fma2(a1b.y, wd10, acc[3][0]);
            acc[3][1] = fma2(a1b.y, wd11, acc[3][1]);
            acc[3][2] = fma2(a1b.y, wd12, acc[3][2]);
            acc[3][3] = fma2(a1b.y, wd13, acc[3][3]);
        }
    }

    // ---- Epilogue (R11-validated per-element form) ----
    if (tcg < 64) {
        const bool is_erase = (tcg < 32);
#pragma unroll
        for (int p = 0; p < 4; p++) {
            const int r0g = row0 + trg * 8 + 2 * p;
            const int r1g = r0g + 1;
            const int b0 = r0g / SS, s0 = r0g - b0 * SS;
            const int b1 = r1g / SS, s1 = r1g - b1 * SS;
#pragma unroll
            for (int c = 0; c < 4; c++) {
                const int col = c0 + c;                  // 0..127 in its matrix
                const int sl = col >> 5;
                const int off = (is_erase ? 0 : 32) + (col & 31);
                float2 f = unpack2(acc[p][c]);
                float v0, v1;
                if (is_erase) {
                    v0 = -1.f / (1.f + __expf(-f.x));
                    v1 = -1.f / (1.f + __expf(-f.y));
                } else {
                    v0 = tanhf(f.x);
                    v1 = tanhf(f.y);
                }
                g_slice[((size_t)(b0 * NSLICE + sl) * SS + s0) * RECF + off] = v0;
                g_slice[((size_t)(b1 * NSLICE + sl) * SS + s1) * RECF + off] = v1;
            }
        }
    } else {
#pragma unroll
        for (int p = 0; p < 4; p++) {
            const int lr = trg * 8 + 2 * p;
#pragma unroll
            for (int c = 0; c < 4; c++) {
                float2 f = unpack2(acc[p][c]);
                sLg[lr    ][c0 + c] = f.x;
                sLg[lr + 1][c0 + c] = f.y;
            }
        }
    }
    __syncthreads();

    if (t < PROWS) {
        float mx = -1e30f;
#pragma unroll
        for (int c = 0; c < CC; c++) mx = fmaxf(mx, sLg[t][c]);
        float sum = 0.f;
#pragma unroll
        for (int c = 0; c < CC; c++) { float e = __expf(sLg[t][c] - mx); sLg[t][c] = e; sum += e; }
        const float inv = 1.f / sum;
#pragma unroll
        for (int c = 0; c < CC; c++) sLg[t][c] *= inv;
    }
    __syncthreads();

    for (int idx = t; idx < PROWS * (CC / 4); idx += PT) {
        const int r = idx >> 4, q = idx & 15;
        const int gr = row0 + r;
        const int b = gr / SS, s = gr - b * SS;
        const float4 o = *(const float4*)&sLg[r][q * 4];
#pragma unroll
        for (int j = 0; j < NSLICE; j++)
            *(float4*)&g_slice[((size_t)(b * NSLICE + j) * SS + s) * RECF + 64 + q * 4] = o;
    }
}

// ---------------------------------------------------------------------------
// Kernel B: sliced scan (UNCHANGED from passing R10).
// ---------------------------------------------------------------------------
__global__ __launch_bounds__(256) void scan_kernel(
    const float* __restrict__ init_value_memory)
{
    extern __shared__ __align__(16) float dsm[];

    const int bs = blockIdx.x;
    const int sl = bs & 3;
    const int b  = bs >> 2;
    const int t  = threadIdx.x;
    const int pg = t >> 4;
    const int cg = t & 15;

    {
        const float4* src = (const float4*)(g_slice + (size_t)bs * SS * RECF);
        float4* dst = (float4*)dsm;
#pragma unroll
        for (int i = 0; i < 25; i++)
            dst[t + i * 256] = src[t + i * 256];
    }

    const int v0 = sl * SLICEV + pg * 2;
    ull m2[4];
    {
        const float4 ra = *(const float4*)(init_value_memory + (v0    ) * CC + cg * 4);
        const float4 rb = *(const float4*)(init_value_memory + (v0 + 1) * CC + cg * 4);
        m2[0] = pack2(ra.x, rb.x);
        m2[1] = pack2(ra.y, rb.y);
        m2[2] = pack2(ra.z, rb.z);
        m2[3] = pack2(ra.w, rb.w);
    }
    __syncthreads();

    const float* sp = dsm;
#pragma unroll 4
    for (int s = 0; s < SS; s++, sp += RECF) {
        const ull ne = *(const ull*)(sp + pg * 2);
        const ull aa = *(const ull*)(sp + 32 + pg * 2);
        const float4 wf = *(const float4*)(sp + 64 + cg * 4);
        const ull w0 = pack2(wf.x, wf.x);
        const ull w1 = pack2(wf.y, wf.y);
        const ull w2 = pack2(wf.z, wf.z);
        const ull w3 = pack2(wf.w, wf.w);
        m2[0] = fma2(w0, fma2(m2[0], ne, aa), m2[0]);
        m2[1] = fma2(w1, fma2(m2[1], ne, aa), m2[1]);
        m2[2] = fma2(w2, fma2(m2[2], ne, aa), m2[2]);
        m2[3] = fma2(w3, fma2(m2[3], ne, aa), m2[3]);
    }

    float* dst0 = g_mem + ((size_t)b * VV + v0) * CC + cg * 4;
    float* dst1 = dst0 + CC;
    float2 f0 = unpack2(m2[0]), f1 = unpack2(m2[1]), f2 = unpack2(m2[2]), f3 = unpack2(m2[3]);
    float4 oa; oa.x = f0.x; oa.y = f1.x; oa.z = f2.x; oa.w = f3.x;
    float4 ob; ob.x = f0.y; ob.y = f1.y; ob.z = f2.y; ob.w = f3.y;
    *(float4*)dst0 = oa;
    *(float4*)dst1 = ob;
}

// ---------------------------------------------------------------------------
// Kernel C: readout (UNCHANGED from passing R10).
// ---------------------------------------------------------------------------
__global__ __launch_bounds__(256) void readout_kernel(
    const float* __restrict__ q_emb,
    const float* __restrict__ key_memory,
    const float* __restrict__ summ_W,
    const float* __restrict__ summ_b,
    const float* __restrict__ out_W,
    const float* __restrict__ out_b,
    const int*   __restrict__ target_id,
    float* __restrict__ out)
{
    __shared__ float sMem[VV][CC + 1];
    __shared__ float sQv[KK];
    __shared__ float sWt[CC];
    __shared__ float sCat[VV + KK];
    __shared__ float sPart[4][CC + 1];
    __shared__ float sRed[8][SUMD + 4];
    __shared__ float sRed2[4];

    const int b    = blockIdx.x;
    const int t    = threadIdx.x;
    const int lane = t & 31;
    const int wid  = t >> 5;

    const float* gm = g_mem + (size_t)b * VV * CC;
#pragma unroll
    for (int i = 0; i < 8; i++) {
        const int idx = t + i * 256;
        const int v = idx >> 4, q = idx & 15;
        const float4 val = *(const float4*)(gm + v * CC + q * 4);
        sMem[v][q * 4 + 0] = val.x;
        sMem[v][q * 4 + 1] = val.y;
        sMem[v][q * 4 + 2] = val.z;
        sMem[v][q * 4 + 3] = val.w;
    }
    if (t < KK) sQv[t] = q_emb[(size_t)target_id[b] * KK + t];
    __syncthreads();

    {
        const int c = t & 63, kg = t >> 6;
        float acc = 0.f;
#pragma unroll
        for (int j = 0; j < 32; j++)
            acc = fmaf(sQv[kg * 32 + j], __ldg(key_memory + (kg * 32 + j) * CC + c), acc);
        sPart[kg][c] = acc;
    }
    __syncthreads();
    if (t < CC) {
        float s = 0.f;
#pragma unroll
        for (int j = 0; j < 4; j++) s += sPart[j][t];
        sWt[t] = s;
    }
    __syncthreads();
    if (t < 32) {
        float l0 = sWt[t], l1 = sWt[t + 32];
        float mx = fmaxf(l0, l1);
#pragma unroll
        for (int off = 16; off > 0; off >>= 1)
            mx = fmaxf(mx, __shfl_xor_sync(0xffffffffu, mx, off));
        float e0 = __expf(l0 - mx), e1 = __expf(l1 - mx);
        float sm = e0 + e1;
#pragma unroll
        for (int off = 16; off > 0; off >>= 1)
            sm += __shfl_xor_sync(0xffffffffu, sm, off);
        const float inv = 1.f / sm;
        sWt[t] = e0 * inv;
        sWt[t + 32] = e1 * inv;
    }
    __syncthreads();

    if (t < VV) {
        float acc = 0.f;
#pragma unroll
        for (int c = 0; c < CC; c++)
            acc = fmaf(sMem[t][c], sWt[c], acc);
        sCat[t] = acc;
    } else {
        sCat[t] = sQv[t - 128];
    }
    __syncthreads();

    {
        float4 acc4 = make_float4(0.f, 0.f, 0.f, 0.f);
#pragma unroll
        for (int j = 0; j < 32; j++) {
            const int row = wid * 32 + j;
            const float x = sCat[row];
            const float4 wr = *(const float4*)(summ_W + row * SUMD + lane * 4);
            acc4.x = fmaf(x, wr.x, acc4.x);
            acc4.y = fmaf(x, wr.y, acc4.y);
            acc4.z = fmaf(x, wr.z, acc4.z);
            acc4.w = fmaf(x, wr.w, acc4.w);
        }
        *(float4*)&sRed[wid][lane * 4] = acc4;
    }
    __syncthreads();

    if (t < SUMD) {
        float s = 0.f;
#pragma unroll
        for (int j = 0; j < 8; j++) s += sRed[j][t];
        const float sm = tanhf(s + summ_b[t]);
        float p = sm * __ldg(out_W + t);
#pragma unroll
        for (int off = 16; off > 0; off >>= 1)
            p += __shfl_down_sync(0xffffffffu, p, off);
        if (lane == 0) sRed2[wid] = p;
    }
    __syncthreads();
    if (t == 0)
        out[b] = sRed2[0] + sRed2[1] + sRed2[2] + sRed2[3] + out_b[0];
}

// ---------------------------------------------------------------------------
extern "C" void kernel_launch(void* const* d_in, const int* in_sizes, int n_in,
                              void* d_out, int out_size)
{
    const float* q_emb      = (const float*)d_in[0];
    const float* i_emb      = (const float*)d_in[1];
    const float* key_memory = (const float*)d_in[2];
    const float* init_vm    = (const float*)d_in[3];
    const float* erase_W    = (const float*)d_in[4];
    const float* erase_b    = (const float*)d_in[5];
    const float* add_W      = (const float*)d_in[6];
    const float* add_b      = (const float*)d_in[7];
    const float* summ_W     = (const float*)d_in[8];
    const float* summ_b     = (const float*)d_in[9];
    const float* out_W      = (const float*)d_in[10];
    const float* out_b      = (const float*)d_in[11];
    const int*   input      = (const int*)d_in[12];
    const int*   target_id  = (const int*)d_in[13];
    float* out = (float*)d_out;

    cudaFuncSetAttribute(precompute_kernel, cudaFuncAttributeMaxDynamicSharedMemorySize, PRE_SMEM);
    cudaFuncSetAttribute(scan_kernel, cudaFuncAttributeMaxDynamicSharedMemorySize, SCAN_SMEM);

    precompute_kernel<<<NROWS / PROWS, PT, PRE_SMEM>>>(
        q_emb, i_emb, key_memory, erase_W, erase_b, add_W, add_b, input);

    scan_kernel<<<BB * NSLICE, 256, SCAN_SMEM>>>(init_vm);

    readout_kernel<<<BB, 256>>>(
        q_emb, key_memory, summ_W, summ_b, out_W, out_b, target_id, out);
}